// round 6
// baseline (speedup 1.0000x reference)
#include <cuda_runtime.h>
#include <cuda_bf16.h>
#include <math.h>
#include <stdint.h>

// ---------------- problem constants ----------------
#define BB   16
#define CC   256
#define HH   56
#define HWSZ 3136
#define WWIN 7
#define NN   49
#define MM   1024
#define NHD  8
#define HID_ 1024
#define NPTS 50176
#define EPSV 1e-5f

// ---------------- device scratch ----------------
__device__ float g_qkv[(size_t)NPTS * 3 * CC];
__device__ float g_o  [(size_t)NPTS * CC];
__device__ __nv_bfloat16 s1h[(size_t)NPTS * CC], s1l[(size_t)NPTS * CC];
__device__ __nv_bfloat16 s2h[(size_t)NPTS * CC], s2l[(size_t)NPTS * CC];
__device__ __nv_bfloat16 ghh[(size_t)NPTS * HID_], ghl[(size_t)NPTS * HID_];
__device__ __nv_bfloat16 wqh[3 * CC * CC], wql[3 * CC * CC];
__device__ __nv_bfloat16 wph[CC * CC],     wpl[CC * CC];
__device__ __nv_bfloat16 w1h[HID_ * CC],   w1l[HID_ * CC];
__device__ __nv_bfloat16 w2h[CC * HID_],   w2l[CC * HID_];
__device__ float g_bias[NHD * NN * NN];

// ================= helpers =================
__device__ __forceinline__ void mma16816(float* c, const uint32_t* a, const uint32_t* b) {
    asm volatile(
        "mma.sync.aligned.m16n8k16.row.col.f32.bf16.bf16.f32 "
        "{%0,%1,%2,%3}, {%4,%5,%6,%7}, {%8,%9}, {%0,%1,%2,%3};"
        : "+f"(c[0]), "+f"(c[1]), "+f"(c[2]), "+f"(c[3])
        : "r"(a[0]), "r"(a[1]), "r"(a[2]), "r"(a[3]), "r"(b[0]), "r"(b[1]));
}
__device__ __forceinline__ void ldsm4(uint32_t* r, uint32_t addr) {
    asm volatile("ldmatrix.sync.aligned.m8n8.x4.shared.b16 {%0,%1,%2,%3}, [%4];"
        : "=r"(r[0]), "=r"(r[1]), "=r"(r[2]), "=r"(r[3]) : "r"(addr));
}
__device__ __forceinline__ uint32_t split2(float x, float y, uint32_t& lo2) {
    __nv_bfloat16 hx = __float2bfloat16(x);
    __nv_bfloat16 hy = __float2bfloat16(y);
    float lx = x - __bfloat162float(hx);
    float ly = y - __bfloat162float(hy);
    __nv_bfloat162 h; h.x = hx; h.y = hy;
    __nv_bfloat162 l; l.x = __float2bfloat16(lx); l.y = __float2bfloat16(ly);
    lo2 = *reinterpret_cast<uint32_t*>(&l);
    return *reinterpret_cast<uint32_t*>(&h);
}
__device__ __forceinline__ uint32_t smem_u32(const void* p) {
    uint32_t a;
    asm("{ .reg .u64 t; cvta.to.shared.u64 t, %1; cvt.u32.u64 %0, t; }" : "=r"(a) : "l"(p));
    return a;
}

// ================= bf16 split GEMM (ldmatrix + reg-staged double buffer) =================
#define SPAD  40
#define TILEH (128 * SPAD)
#define GSMEM (8 * TILEH * 2)    // 81920 bytes

__global__ void __launch_bounds__(256, 1)
k_gemm(const __nv_bfloat16* __restrict__ Wh, const __nv_bfloat16* __restrict__ Wl,
       const float* __restrict__ bias,
       const __nv_bfloat16* __restrict__ Xh, const __nv_bfloat16* __restrict__ Xl,
       float* __restrict__ out, __nv_bfloat16* __restrict__ outh, __nv_bfloat16* __restrict__ outl,
       int IC, int OC, int mode)
{
    extern __shared__ __align__(16) __nv_bfloat16 sm[];
    __nv_bfloat16* Ah = sm;
    __nv_bfloat16* Al = sm + 2 * TILEH;
    __nv_bfloat16* Bh = sm + 4 * TILEH;
    __nv_bfloat16* Bl = sm + 6 * TILEH;
    const uint32_t sbAh = smem_u32(Ah), sbAl = smem_u32(Al);
    const uint32_t sbBh = smem_u32(Bh), sbBl = smem_u32(Bl);

    const int tid = threadIdx.x, lane = tid & 31, wid = tid >> 5;
    const int p0 = blockIdx.x * 128, o0 = blockIdx.y * 128;
    const int wm = (wid & 1) * 64, wn = (wid >> 1) * 32;
    const int g = lane >> 2, t = lane & 3;
    const int lrow = tid >> 2, lc8 = (tid & 3) << 3;

    // ldmatrix per-lane source coordinates
    const int a_row = (lane & 7) + ((lane >> 3) & 1) * 8;   // 0..15
    const int a_col = (lane >> 4) * 8;                       // 0 | 8
    const int b_row = (lane & 7) + (lane >> 4) * 8;          // 0..15 (j-pair rows)
    const int b_col = ((lane >> 3) & 1) * 8;                 // 0 | 8

    float acc[4][4][4];
    #pragma unroll
    for (int i = 0; i < 4; i++)
        #pragma unroll
        for (int j = 0; j < 4; j++)
            #pragma unroll
            for (int q = 0; q < 4; q++) acc[i][j][q] = 0.f;

    uint4 rxh[2], rxl[2], rwh[2], rwl[2];

    auto fetch = [&](int kt) {
        int c0 = kt * 32;
        #pragma unroll
        for (int i = 0; i < 2; ++i) {
            int r = lrow + i * 64;
            size_t gx = (size_t)(p0 + r) * IC + c0 + lc8;
            size_t gw = (size_t)(o0 + r) * IC + c0 + lc8;
            rxh[i] = *reinterpret_cast<const uint4*>(Xh + gx);
            rxl[i] = *reinterpret_cast<const uint4*>(Xl + gx);
            rwh[i] = *reinterpret_cast<const uint4*>(Wh + gw);
            rwl[i] = *reinterpret_cast<const uint4*>(Wl + gw);
        }
    };
    auto stash = [&](int buf) {
        #pragma unroll
        for (int i = 0; i < 2; ++i) {
            int r = lrow + i * 64;
            int ha = buf * TILEH + r * SPAD + lc8;
            *reinterpret_cast<uint4*>(&Ah[ha]) = rxh[i];
            *reinterpret_cast<uint4*>(&Al[ha]) = rxl[i];
            *reinterpret_cast<uint4*>(&Bh[ha]) = rwh[i];
            *reinterpret_cast<uint4*>(&Bl[ha]) = rwl[i];
        }
    };
    auto compute = [&](int buf) {
        #pragma unroll
        for (int k0 = 0; k0 < 32; k0 += 16) {
            uint32_t ah[4][4], al[4][4], bhj[2][4], blj[2][4];
            // A fragments: tile i at rows wm+16i, cols k0..k0+15
            #pragma unroll
            for (int i = 0; i < 4; i++) {
                uint32_t off = (uint32_t)((buf * TILEH + (wm + i * 16 + a_row) * SPAD + k0 + a_col) * 2);
                ldsm4(ah[i], sbAh + off);
                ldsm4(al[i], sbAl + off);
            }
            // B fragments: j-pair j2 at rows wn+16*j2, cols k0..k0+15
            #pragma unroll
            for (int j2 = 0; j2 < 2; j2++) {
                uint32_t off = (uint32_t)((buf * TILEH + (wn + j2 * 16 + b_row) * SPAD + k0 + b_col) * 2);
                ldsm4(bhj[j2], sbBh + off);
                ldsm4(blj[j2], sbBl + off);
            }
            #pragma unroll
            for (int i = 0; i < 4; i++)
                #pragma unroll
                for (int j = 0; j < 4; j++) mma16816(acc[i][j], ah[i], &bhj[j >> 1][(j & 1) * 2]);
            #pragma unroll
            for (int i = 0; i < 4; i++)
                #pragma unroll
                for (int j = 0; j < 4; j++) mma16816(acc[i][j], ah[i], &blj[j >> 1][(j & 1) * 2]);
            #pragma unroll
            for (int i = 0; i < 4; i++)
                #pragma unroll
                for (int j = 0; j < 4; j++) mma16816(acc[i][j], al[i], &bhj[j >> 1][(j & 1) * 2]);
        }
    };

    fetch(0); stash(0);
    __syncthreads();
    const int KT = IC >> 5;
    for (int kt = 0; kt < KT; ++kt) {
        int buf = kt & 1;
        if (kt + 1 < KT) fetch(kt + 1);
        compute(buf);
        if (kt + 1 < KT) stash(buf ^ 1);
        __syncthreads();
    }

    // epilogue
    #pragma unroll
    for (int j = 0; j < 4; j++) {
        int col = o0 + wn + j * 8 + 2 * t;
        float b0 = bias[col], b1 = bias[col + 1];
        #pragma unroll
        for (int i = 0; i < 4; i++) {
            int r0 = p0 + wm + i * 16 + g;
            float v0 = acc[i][j][0] + b0, v1 = acc[i][j][1] + b1;
            float v2 = acc[i][j][2] + b0, v3 = acc[i][j][3] + b1;
            if (mode == 2) {
                v0 = 0.5f * v0 * (1.f + erff(v0 * 0.70710678118654752f));
                v1 = 0.5f * v1 * (1.f + erff(v1 * 0.70710678118654752f));
                v2 = 0.5f * v2 * (1.f + erff(v2 * 0.70710678118654752f));
                v3 = 0.5f * v3 * (1.f + erff(v3 * 0.70710678118654752f));
            }
            if (mode == 0) {
                *reinterpret_cast<float2*>(&out[(size_t)r0 * OC + col])       = make_float2(v0, v1);
                *reinterpret_cast<float2*>(&out[(size_t)(r0 + 8) * OC + col]) = make_float2(v2, v3);
            } else {
                uint32_t l0, l1;
                uint32_t h0 = split2(v0, v1, l0);
                uint32_t h1 = split2(v2, v3, l1);
                *reinterpret_cast<uint32_t*>(&outh[(size_t)r0 * OC + col])       = h0;
                *reinterpret_cast<uint32_t*>(&outl[(size_t)r0 * OC + col])       = l0;
                *reinterpret_cast<uint32_t*>(&outh[(size_t)(r0 + 8) * OC + col]) = h1;
                *reinterpret_cast<uint32_t*>(&outl[(size_t)(r0 + 8) * OC + col]) = l1;
            }
        }
    }
}

// ================= weight split =================
__global__ void k_wsplit(const float* __restrict__ w, __nv_bfloat16* __restrict__ wh,
                         __nv_bfloat16* __restrict__ wl, int n) {
    int i = blockIdx.x * blockDim.x + threadIdx.x;
    if (i >= n) return;
    float v = w[i];
    __nv_bfloat16 h = __float2bfloat16(v);
    wh[i] = h;
    wl[i] = __float2bfloat16(v - __bfloat162float(h));
}

// ================= relative-position bias =================
__global__ void k_bias(const float* __restrict__ table, float* __restrict__ bias) {
    int i = blockIdx.x * blockDim.x + threadIdx.x;
    if (i >= NHD * NN * NN) return;
    int h = i / (NN * NN);
    int rem = i % (NN * NN);
    int n = rem / NN, k = rem % NN;
    int dr = n / WWIN - k / WWIN + (WWIN - 1);
    int dc = n % WWIN - k % WWIN + (WWIN - 1);
    bias[i] = table[(dr * (2 * WWIN - 1) + dc) * NHD + h];
}

// ================= channel LayerNorm -> split bf16 (pt, C) =================
template <bool BLOCKED>
__global__ void k_ln(const float* __restrict__ x, const float* __restrict__ w,
                     const float* __restrict__ b,
                     __nv_bfloat16* __restrict__ oh, __nv_bfloat16* __restrict__ ol) {
    int blk = blockIdx.x;
    int w0  = (blk & 1) * 28;
    int bh  = blk >> 1;
    int h   = bh % HH;
    int bb  = bh / HH;
    int tx = threadIdx.x, ty = threadIdx.y;
    int wpos = w0 + tx;

    const float* xb = x + (size_t)bb * CC * HWSZ + h * HH + wpos;

    float s = 0.f, s2 = 0.f;
    #pragma unroll
    for (int c = ty; c < CC; c += 8) {
        float v = xb[(size_t)c * HWSZ];
        s += v; s2 += v * v;
    }
    __shared__ float sh_s[8][28], sh_s2[8][28];
    __shared__ float sh_mu[28], sh_rs[28];
    sh_s[ty][tx] = s; sh_s2[ty][tx] = s2;
    __syncthreads();
    if (ty == 0) {
        float ts = 0.f, ts2 = 0.f;
        #pragma unroll
        for (int j = 0; j < 8; j++) { ts += sh_s[j][tx]; ts2 += sh_s2[j][tx]; }
        float mu  = ts * (1.f / CC);
        float var = ts2 * (1.f / CC) - mu * mu;
        sh_mu[tx] = mu; sh_rs[tx] = rsqrtf(var + EPSV);
    }
    __syncthreads();
    float mu = sh_mu[tx], rs = sh_rs[tx];

    size_t pt;
    if (BLOCKED) {
        int m = bb * 64 + (h / WWIN) * 8 + (wpos / WWIN);
        int n = (h % WWIN) * WWIN + (wpos % WWIN);
        pt = (size_t)m * NN + n;
    } else {
        pt = (size_t)bb * HWSZ + h * HH + wpos;
    }
    __nv_bfloat16* ohb = oh + pt * CC;
    __nv_bfloat16* olb = ol + pt * CC;
    #pragma unroll
    for (int c = ty; c < CC; c += 8) {
        float v = (xb[(size_t)c * HWSZ] - mu) * rs * w[c] + b[c];
        __nv_bfloat16 hv = __float2bfloat16(v);
        ohb[c] = hv;
        olb[c] = __float2bfloat16(v - __bfloat162float(hv));
    }
}

// ================= attention core (R3 structure, split bf16 output) =================
#define QPAD 36
__global__ void k_attn(const float* __restrict__ qkv, const float* __restrict__ bias,
                       __nv_bfloat16* __restrict__ outh, __nv_bfloat16* __restrict__ outl) {
    int m = blockIdx.x >> 3;
    int h = blockIdx.x & 7;

    __shared__ float sq[NN * QPAD], sk[NN * QPAD], sv[NN * QPAD];
    __shared__ float at[NN * 52];

    int tid = threadIdx.x;
    const float scale = 0.17677669529663687f;
    const float* baseq = qkv + (size_t)(m * NN) * (3 * CC) + h * 32;
    #pragma unroll 2
    for (int i = tid; i < NN * 8; i += 256) {
        int n = i >> 3, d4 = (i & 7) << 2;
        const float* rp = baseq + (size_t)n * (3 * CC);
        float4 q4 = *reinterpret_cast<const float4*>(rp + d4);
        float4 k4 = *reinterpret_cast<const float4*>(rp + CC + d4);
        float4 v4 = *reinterpret_cast<const float4*>(rp + 2 * CC + d4);
        q4.x *= scale; q4.y *= scale; q4.z *= scale; q4.w *= scale;
        *reinterpret_cast<float4*>(&sq[n * QPAD + d4]) = q4;
        *reinterpret_cast<float4*>(&sk[n * QPAD + d4]) = k4;
        *reinterpret_cast<float4*>(&sv[n * QPAD + d4]) = v4;
    }
    __syncthreads();

    const float* bh = bias + h * NN * NN;
    for (int i = tid; i < NN * NN; i += 256) {
        int n = i / NN, kk = i % NN;
        const float4* qr = reinterpret_cast<const float4*>(&sq[n * QPAD]);
        const float4* kr = reinterpret_cast<const float4*>(&sk[kk * QPAD]);
        float s = 0.f;
        #pragma unroll
        for (int d = 0; d < 8; d++) {
            float4 a = qr[d], b = kr[d];
            s += a.x * b.x + a.y * b.y + a.z * b.z + a.w * b.w;
        }
        at[n * 52 + kk] = s + bh[i];
    }
    __syncthreads();

    int warp = tid >> 5, lane = tid & 31;
    for (int n = warp; n < NN; n += 8) {
        float v0 = at[n * 52 + lane];
        float v1 = (lane + 32 < NN) ? at[n * 52 + lane + 32] : -INFINITY;
        float mx = fmaxf(v0, v1);
        #pragma unroll
        for (int o = 16; o; o >>= 1) mx = fmaxf(mx, __shfl_xor_sync(0xffffffffu, mx, o));
        float e0 = __expf(v0 - mx);
        float e1 = (lane + 32 < NN) ? __expf(v1 - mx) : 0.f;
        float s = e0 + e1;
        #pragma unroll
        for (int o = 16; o; o >>= 1) s += __shfl_xor_sync(0xffffffffu, s, o);
        float inv = 1.f / s;
        at[n * 52 + lane] = e0 * inv;
        if (lane + 32 < NN) at[n * 52 + lane + 32] = e1 * inv;
    }
    __syncthreads();

    for (int i = tid; i < NN * 8; i += 256) {
        int n = i >> 3, d4 = (i & 7) << 2;
        float4 accv = make_float4(0.f, 0.f, 0.f, 0.f);
        #pragma unroll 7
        for (int kk = 0; kk < NN; kk++) {
            float wv = at[n * 52 + kk];
            float4 v4 = *reinterpret_cast<const float4*>(&sv[kk * QPAD + d4]);
            accv.x += wv * v4.x; accv.y += wv * v4.y;
            accv.z += wv * v4.z; accv.w += wv * v4.w;
        }
        size_t o = (size_t)(m * NN + n) * CC + h * 32 + d4;
        uint32_t l0, l1;
        uint32_t h0 = split2(accv.x, accv.y, l0);
        uint32_t h1 = split2(accv.z, accv.w, l1);
        *reinterpret_cast<uint2*>(&outh[o]) = make_uint2(h0, h1);
        *reinterpret_cast<uint2*>(&outl[o]) = make_uint2(l0, l1);
    }
}

// ================= residuals =================
__global__ void k_resid(const float* __restrict__ x, const float* __restrict__ y,
                        float* __restrict__ out) {
    int i = blockIdx.x * blockDim.x + threadIdx.x;
    if (i >= BB * CC * HWSZ) return;
    int w = i % HH; int t = i / HH;
    int h = t % HH;  t /= HH;
    int c = t % CC;  int b = t / CC;
    int m = b * 64 + (h / WWIN) * 8 + (w / WWIN);
    int n = (h % WWIN) * WWIN + (w % WWIN);
    out[i] = x[i] + y[(size_t)(m * NN + n) * CC + c];
}
__global__ void k_resid2(float* __restrict__ out, const float* __restrict__ z) {
    int i = blockIdx.x * blockDim.x + threadIdx.x;
    if (i >= BB * CC * HWSZ) return;
    int hw = i % HWSZ;
    int c  = (i / HWSZ) % CC;
    int b  = i / (HWSZ * CC);
    out[i] += z[((size_t)b * HWSZ + hw) * CC + c];
}

// ================= host launcher =================
extern "C" void kernel_launch(void* const* d_in, const int* in_sizes, int n_in,
                              void* d_out, int out_size) {
    const float* x      = (const float*)d_in[0];
    const float* ln1_w  = (const float*)d_in[1];
    const float* ln1_b  = (const float*)d_in[2];
    const float* ln2_w  = (const float*)d_in[3];
    const float* ln2_b  = (const float*)d_in[4];
    const float* qkv_w  = (const float*)d_in[5];
    const float* qkv_b  = (const float*)d_in[6];
    const float* proj_w = (const float*)d_in[7];
    const float* proj_b = (const float*)d_in[8];
    const float* table  = (const float*)d_in[9];
    const float* fc1_w  = (const float*)d_in[10];
    const float* fc1_b  = (const float*)d_in[11];
    const float* fc2_w  = (const float*)d_in[12];
    const float* fc2_b  = (const float*)d_in[13];
    float* out = (float*)d_out;

    float *p_qkv, *p_o, *p_bias;
    __nv_bfloat16 *p_s1h, *p_s1l, *p_s2h, *p_s2l, *p_ghh, *p_ghl;
    __nv_bfloat16 *p_wqh, *p_wql, *p_wph, *p_wpl, *p_w1h, *p_w1l, *p_w2h, *p_w2l;
    cudaGetSymbolAddress((void**)&p_qkv, g_qkv);
    cudaGetSymbolAddress((void**)&p_o,   g_o);
    cudaGetSymbolAddress((void**)&p_bias,g_bias);
    cudaGetSymbolAddress((void**)&p_s1h, s1h); cudaGetSymbolAddress((void**)&p_s1l, s1l);
    cudaGetSymbolAddress((void**)&p_s2h, s2h); cudaGetSymbolAddress((void**)&p_s2l, s2l);
    cudaGetSymbolAddress((void**)&p_ghh, ghh); cudaGetSymbolAddress((void**)&p_ghl, ghl);
    cudaGetSymbolAddress((void**)&p_wqh, wqh); cudaGetSymbolAddress((void**)&p_wql, wql);
    cudaGetSymbolAddress((void**)&p_wph, wph); cudaGetSymbolAddress((void**)&p_wpl, wpl);
    cudaGetSymbolAddress((void**)&p_w1h, w1h); cudaGetSymbolAddress((void**)&p_w1l, w1l);
    cudaGetSymbolAddress((void**)&p_w2h, w2h); cudaGetSymbolAddress((void**)&p_w2l, w2l);

    cudaFuncSetAttribute(k_gemm, cudaFuncAttributeMaxDynamicSharedMemorySize, GSMEM);

    k_bias<<<(NHD * NN * NN + 255) / 256, 256>>>(table, p_bias);
    k_wsplit<<<(3 * CC * CC + 255) / 256, 256>>>(qkv_w, p_wqh, p_wql, 3 * CC * CC);
    k_wsplit<<<(CC * CC + 255) / 256, 256>>>(proj_w, p_wph, p_wpl, CC * CC);
    k_wsplit<<<(HID_ * CC + 255) / 256, 256>>>(fc1_w, p_w1h, p_w1l, HID_ * CC);
    k_wsplit<<<(CC * HID_ + 255) / 256, 256>>>(fc2_w, p_w2h, p_w2l, CC * HID_);

    k_ln<true><<<BB * HH * 2, dim3(28, 8)>>>(x, ln1_w, ln1_b, p_s1h, p_s1l);

    // attention pass 1
    k_gemm<<<dim3(NPTS / 128, 6), 256, GSMEM>>>(p_wqh, p_wql, qkv_b, p_s1h, p_s1l,
                                                p_qkv, nullptr, nullptr, CC, 3 * CC, 0);
    k_attn<<<MM * NHD, 256>>>(p_qkv, p_bias, p_s2h, p_s2l);
    k_gemm<<<dim3(NPTS / 128, 2), 256, GSMEM>>>(p_wph, p_wpl, proj_b, p_s2h, p_s2l,
                                                nullptr, p_s1h, p_s1l, CC, CC, 1);

    // attention pass 2
    k_gemm<<<dim3(NPTS / 128, 6), 256, GSMEM>>>(p_wqh, p_wql, qkv_b, p_s1h, p_s1l,
                                                p_qkv, nullptr, nullptr, CC, 3 * CC, 0);
    k_attn<<<MM * NHD, 256>>>(p_qkv, p_bias, p_s2h, p_s2l);
    k_gemm<<<dim3(NPTS / 128, 2), 256, GSMEM>>>(p_wph, p_wpl, proj_b, p_s2h, p_s2l,
                                                p_o, nullptr, nullptr, CC, CC, 0);

    // residual + unblock
    k_resid<<<(BB * CC * HWSZ + 255) / 256, 256>>>(x, p_o, out);

    // LN2 -> split (pt, C)
    k_ln<false><<<BB * HH * 2, dim3(28, 8)>>>(out, ln2_w, ln2_b, p_s1h, p_s1l);

    // MLP
    k_gemm<<<dim3(NPTS / 128, HID_ / 128), 256, GSMEM>>>(p_w1h, p_w1l, fc1_b, p_s1h, p_s1l,
                                                         nullptr, p_ghh, p_ghl, CC, HID_, 2);
    k_gemm<<<dim3(NPTS / 128, CC / 128), 256, GSMEM>>>(p_w2h, p_w2l, fc2_b, p_ghh, p_ghl,
                                                       p_o, nullptr, nullptr, HID_, CC, 0);
    k_resid2<<<(BB * CC * HWSZ + 255) / 256, 256>>>(out, p_o);
}

// round 7
// speedup vs baseline: 1.1388x; 1.1388x over previous
#include <cuda_runtime.h>
#include <cuda_bf16.h>
#include <math.h>
#include <stdint.h>

// ---------------- problem constants ----------------
#define BB   16
#define CC   256
#define HH   56
#define HWSZ 3136
#define WWIN 7
#define NN   49
#define MM   1024
#define NHD  8
#define HID_ 1024
#define NPTS 50176
#define EPSV 1e-5f

// ---------------- device scratch ----------------
__device__ float g_xf [(size_t)NPTS * CC];
__device__ float g_qkv[(size_t)NPTS * 3 * CC];
__device__ float g_o  [(size_t)NPTS * CC];
__device__ float g_y1 [(size_t)NPTS * CC];
__device__ float g_ln2[(size_t)NPTS * CC];
__device__ float g_hid[(size_t)NPTS * HID_];
__device__ float g_bias[NHD * NN * NN];

// ================= helpers =================
__device__ __forceinline__ void mma16816(float* c, const uint32_t* a, const uint32_t* b) {
    asm volatile(
        "mma.sync.aligned.m16n8k16.row.col.f32.bf16.bf16.f32 "
        "{%0,%1,%2,%3}, {%4,%5,%6,%7}, {%8,%9}, {%0,%1,%2,%3};"
        : "+f"(c[0]), "+f"(c[1]), "+f"(c[2]), "+f"(c[3])
        : "r"(a[0]), "r"(a[1]), "r"(a[2]), "r"(a[3]), "r"(b[0]), "r"(b[1]));
}
__device__ __forceinline__ void ldsm4(uint32_t* r, uint32_t addr) {
    asm volatile("ldmatrix.sync.aligned.m8n8.x4.shared.b16 {%0,%1,%2,%3}, [%4];"
        : "=r"(r[0]), "=r"(r[1]), "=r"(r[2]), "=r"(r[3]) : "r"(addr));
}
__device__ __forceinline__ uint32_t split2(float x, float y, uint32_t& lo2) {
    __nv_bfloat16 hx = __float2bfloat16(x);
    __nv_bfloat16 hy = __float2bfloat16(y);
    float lx = x - __bfloat162float(hx);
    float ly = y - __bfloat162float(hy);
    __nv_bfloat162 h; h.x = hx; h.y = hy;
    __nv_bfloat162 l; l.x = __float2bfloat16(lx); l.y = __float2bfloat16(ly);
    lo2 = *reinterpret_cast<uint32_t*>(&l);
    return *reinterpret_cast<uint32_t*>(&h);
}
__device__ __forceinline__ uint32_t smem_u32(const void* p) {
    uint32_t a;
    asm("{ .reg .u64 t; cvta.to.shared.u64 t, %1; cvt.u32.u64 %0, t; }" : "=r"(a) : "l"(p));
    return a;
}

// ================= bf16 split GEMM (R3 dataflow + ldmatrix) =================
#define SPAD  40
#define TILEH (128 * SPAD)
#define GSMEM (8 * TILEH * 2)    // 81920 bytes

__global__ void __launch_bounds__(256, 1)
k_gemm(const float* __restrict__ W, const float* __restrict__ bias,
       const float* __restrict__ X, float* __restrict__ out,
       int IC, int OC, int gelu)
{
    extern __shared__ __align__(16) __nv_bfloat16 sm[];
    __nv_bfloat16* Ahi = sm;
    __nv_bfloat16* Alo = sm + 2 * TILEH;
    __nv_bfloat16* Bhi = sm + 4 * TILEH;
    __nv_bfloat16* Blo = sm + 6 * TILEH;
    const uint32_t sbAh = smem_u32(Ahi), sbAl = smem_u32(Alo);
    const uint32_t sbBh = smem_u32(Bhi), sbBl = smem_u32(Blo);

    const int tid = threadIdx.x, lane = tid & 31, wid = tid >> 5;
    const int p0 = blockIdx.x * 128, o0 = blockIdx.y * 128;
    const int wm = (wid & 1) * 64, wn = (wid >> 1) * 32;
    const int g = lane >> 2, t = lane & 3;
    const int lrow = tid >> 3, lc4 = (tid & 7) << 2;

    // ldmatrix per-lane source coordinates (verified in R6)
    const int a_row = (lane & 7) + ((lane >> 3) & 1) * 8;
    const int a_col = (lane >> 4) * 8;
    const int b_row = (lane & 7) + (lane >> 4) * 8;
    const int b_col = ((lane >> 3) & 1) * 8;

    float acc[4][4][4];
    #pragma unroll
    for (int i = 0; i < 4; i++)
        #pragma unroll
        for (int j = 0; j < 4; j++)
            #pragma unroll
            for (int q = 0; q < 4; q++) acc[i][j][q] = 0.f;

    float4 ra[4], rb[4];

    auto fetch = [&](int kt) {
        int c0 = kt * 32;
        #pragma unroll
        for (int it = 0; it < 4; ++it) {
            int r = lrow + it * 32;
            ra[it] = *reinterpret_cast<const float4*>(X + (size_t)(p0 + r) * IC + c0 + lc4);
            rb[it] = *reinterpret_cast<const float4*>(W + (size_t)(o0 + r) * IC + c0 + lc4);
        }
    };
    auto stash = [&](int buf) {
        #pragma unroll
        for (int it = 0; it < 4; ++it) {
            int r = lrow + it * 32;
            int ha = buf * TILEH + r * SPAD + lc4;
            uint32_t l0, l1, h0, h1;
            h0 = split2(ra[it].x, ra[it].y, l0);
            h1 = split2(ra[it].z, ra[it].w, l1);
            *reinterpret_cast<uint2*>(&Ahi[ha]) = make_uint2(h0, h1);
            *reinterpret_cast<uint2*>(&Alo[ha]) = make_uint2(l0, l1);
            h0 = split2(rb[it].x, rb[it].y, l0);
            h1 = split2(rb[it].z, rb[it].w, l1);
            *reinterpret_cast<uint2*>(&Bhi[ha]) = make_uint2(h0, h1);
            *reinterpret_cast<uint2*>(&Blo[ha]) = make_uint2(l0, l1);
        }
    };
    auto compute = [&](int buf) {
        #pragma unroll
        for (int k0 = 0; k0 < 32; k0 += 16) {
            uint32_t ah[4][4], al[4][4], bhj[2][4], blj[2][4];
            #pragma unroll
            for (int i = 0; i < 4; i++) {
                uint32_t off = (uint32_t)((buf * TILEH + (wm + i * 16 + a_row) * SPAD + k0 + a_col) * 2);
                ldsm4(ah[i], sbAh + off);
                ldsm4(al[i], sbAl + off);
            }
            #pragma unroll
            for (int j2 = 0; j2 < 2; j2++) {
                uint32_t off = (uint32_t)((buf * TILEH + (wn + j2 * 16 + b_row) * SPAD + k0 + b_col) * 2);
                ldsm4(bhj[j2], sbBh + off);
                ldsm4(blj[j2], sbBl + off);
            }
            #pragma unroll
            for (int i = 0; i < 4; i++)
                #pragma unroll
                for (int j = 0; j < 4; j++) mma16816(acc[i][j], ah[i], &bhj[j >> 1][(j & 1) * 2]);
            #pragma unroll
            for (int i = 0; i < 4; i++)
                #pragma unroll
                for (int j = 0; j < 4; j++) mma16816(acc[i][j], ah[i], &blj[j >> 1][(j & 1) * 2]);
            #pragma unroll
            for (int i = 0; i < 4; i++)
                #pragma unroll
                for (int j = 0; j < 4; j++) mma16816(acc[i][j], al[i], &bhj[j >> 1][(j & 1) * 2]);
        }
    };

    fetch(0); stash(0);
    __syncthreads();
    const int KT = IC >> 5;
    for (int kt = 0; kt < KT; ++kt) {
        int buf = kt & 1;
        if (kt + 1 < KT) fetch(kt + 1);
        compute(buf);
        if (kt + 1 < KT) stash(buf ^ 1);
        __syncthreads();
    }

    // epilogue
    #pragma unroll
    for (int j = 0; j < 4; j++) {
        int col = o0 + wn + j * 8 + 2 * t;
        float b0 = bias[col], b1 = bias[col + 1];
        #pragma unroll
        for (int i = 0; i < 4; i++) {
            int r0 = p0 + wm + i * 16 + g;
            float v0 = acc[i][j][0] + b0, v1 = acc[i][j][1] + b1;
            float v2 = acc[i][j][2] + b0, v3 = acc[i][j][3] + b1;
            if (gelu) {
                v0 = 0.5f * v0 * (1.f + erff(v0 * 0.70710678118654752f));
                v1 = 0.5f * v1 * (1.f + erff(v1 * 0.70710678118654752f));
                v2 = 0.5f * v2 * (1.f + erff(v2 * 0.70710678118654752f));
                v3 = 0.5f * v3 * (1.f + erff(v3 * 0.70710678118654752f));
            }
            *reinterpret_cast<float2*>(&out[(size_t)r0 * OC + col])       = make_float2(v0, v1);
            *reinterpret_cast<float2*>(&out[(size_t)(r0 + 8) * OC + col]) = make_float2(v2, v3);
        }
    }
}

// ================= relative-position bias =================
__global__ void k_bias(const float* __restrict__ table, float* __restrict__ bias) {
    int i = blockIdx.x * blockDim.x + threadIdx.x;
    if (i >= NHD * NN * NN) return;
    int h = i / (NN * NN);
    int rem = i % (NN * NN);
    int n = rem / NN, k = rem % NN;
    int dr = n / WWIN - k / WWIN + (WWIN - 1);
    int dc = n % WWIN - k % WWIN + (WWIN - 1);
    bias[i] = table[(dr * (2 * WWIN - 1) + dc) * NHD + h];
}

// ================= channel LayerNorm: NCHW in, (pt, C) out =================
template <bool BLOCKED>
__global__ void k_ln(const float* __restrict__ x, const float* __restrict__ w,
                     const float* __restrict__ b, float* __restrict__ out) {
    int blk = blockIdx.x;
    int w0  = (blk & 1) * 28;
    int bh  = blk >> 1;
    int h   = bh % HH;
    int bb  = bh / HH;
    int tx = threadIdx.x, ty = threadIdx.y;
    int wpos = w0 + tx;

    const float* xb = x + (size_t)bb * CC * HWSZ + h * HH + wpos;

    float s = 0.f, s2 = 0.f;
    #pragma unroll
    for (int c = ty; c < CC; c += 8) {
        float v = xb[(size_t)c * HWSZ];
        s += v; s2 += v * v;
    }
    __shared__ float sh_s[8][28], sh_s2[8][28];
    __shared__ float sh_mu[28], sh_rs[28];
    sh_s[ty][tx] = s; sh_s2[ty][tx] = s2;
    __syncthreads();
    if (ty == 0) {
        float ts = 0.f, ts2 = 0.f;
        #pragma unroll
        for (int j = 0; j < 8; j++) { ts += sh_s[j][tx]; ts2 += sh_s2[j][tx]; }
        float mu  = ts * (1.f / CC);
        float var = ts2 * (1.f / CC) - mu * mu;
        sh_mu[tx] = mu; sh_rs[tx] = rsqrtf(var + EPSV);
    }
    __syncthreads();
    float mu = sh_mu[tx], rs = sh_rs[tx];

    size_t pt;
    if (BLOCKED) {
        int m = bb * 64 + (h / WWIN) * 8 + (wpos / WWIN);
        int n = (h % WWIN) * WWIN + (wpos % WWIN);
        pt = (size_t)m * NN + n;
    } else {
        pt = (size_t)bb * HWSZ + h * HH + wpos;
    }
    float* ob = out + pt * CC;
    #pragma unroll
    for (int c = ty; c < CC; c += 8)
        ob[c] = (xb[(size_t)c * HWSZ] - mu) * rs * w[c] + b[c];
}

// ================= attention core (R3 verbatim) =================
#define QPAD 36
__global__ void k_attn(const float* __restrict__ qkv, const float* __restrict__ bias,
                       float* __restrict__ out) {
    int m = blockIdx.x >> 3;
    int h = blockIdx.x & 7;

    __shared__ float sq[NN * QPAD], sk[NN * QPAD], sv[NN * QPAD];
    __shared__ float at[NN * 52];

    int tid = threadIdx.x;
    const float* baseq = qkv + (size_t)(m * NN) * (3 * CC) + h * 32;
    #pragma unroll 2
    for (int i = tid; i < NN * 8; i += 256) {
        int n = i >> 3, d4 = (i & 7) << 2;
        const float* rp = baseq + (size_t)n * (3 * CC);
        float4 q4 = *reinterpret_cast<const float4*>(rp + d4);
        float4 k4 = *reinterpret_cast<const float4*>(rp + CC + d4);
        float4 v4 = *reinterpret_cast<const float4*>(rp + 2 * CC + d4);
        *reinterpret_cast<float4*>(&sq[n * QPAD + d4]) = q4;
        *reinterpret_cast<float4*>(&sk[n * QPAD + d4]) = k4;
        *reinterpret_cast<float4*>(&sv[n * QPAD + d4]) = v4;
    }
    __syncthreads();

    const float* bh = bias + h * NN * NN;
    const float scale = 0.17677669529663687f;
    for (int i = tid; i < NN * NN; i += 256) {
        int n = i / NN, kk = i % NN;
        const float4* qr = reinterpret_cast<const float4*>(&sq[n * QPAD]);
        const float4* kr = reinterpret_cast<const float4*>(&sk[kk * QPAD]);
        float s = 0.f;
        #pragma unroll
        for (int d = 0; d < 8; d++) {
            float4 a = qr[d], b = kr[d];
            s += a.x * b.x + a.y * b.y + a.z * b.z + a.w * b.w;
        }
        at[n * 52 + kk] = s * scale + bh[i];
    }
    __syncthreads();

    int warp = tid >> 5, lane = tid & 31;
    for (int n = warp; n < NN; n += 8) {
        float v0 = at[n * 52 + lane];
        float v1 = (lane + 32 < NN) ? at[n * 52 + lane + 32] : -INFINITY;
        float mx = fmaxf(v0, v1);
        #pragma unroll
        for (int o = 16; o; o >>= 1) mx = fmaxf(mx, __shfl_xor_sync(0xffffffffu, mx, o));
        float e0 = __expf(v0 - mx);
        float e1 = (lane + 32 < NN) ? __expf(v1 - mx) : 0.f;
        float s = e0 + e1;
        #pragma unroll
        for (int o = 16; o; o >>= 1) s += __shfl_xor_sync(0xffffffffu, s, o);
        float inv = 1.f / s;
        at[n * 52 + lane] = e0 * inv;
        if (lane + 32 < NN) at[n * 52 + lane + 32] = e1 * inv;
    }
    __syncthreads();

    for (int i = tid; i < NN * 8; i += 256) {
        int n = i >> 3, d4 = (i & 7) << 2;
        float4 accv = make_float4(0.f, 0.f, 0.f, 0.f);
        #pragma unroll 7
        for (int kk = 0; kk < NN; kk++) {
            float wv = at[n * 52 + kk];
            float4 v4 = *reinterpret_cast<const float4*>(&sv[kk * QPAD + d4]);
            accv.x += wv * v4.x; accv.y += wv * v4.y;
            accv.z += wv * v4.z; accv.w += wv * v4.w;
        }
        *reinterpret_cast<float4*>(&out[(size_t)(m * NN + n) * CC + h * 32 + d4]) = accv;
    }
}

// ================= residuals =================
__global__ void k_resid(const float* __restrict__ x, const float* __restrict__ y,
                        float* __restrict__ out) {
    int i = blockIdx.x * blockDim.x + threadIdx.x;
    if (i >= BB * CC * HWSZ) return;
    int w = i % HH; int t = i / HH;
    int h = t % HH;  t /= HH;
    int c = t % CC;  int b = t / CC;
    int m = b * 64 + (h / WWIN) * 8 + (w / WWIN);
    int n = (h % WWIN) * WWIN + (w % WWIN);
    out[i] = x[i] + y[(size_t)(m * NN + n) * CC + c];
}
__global__ void k_resid2(float* __restrict__ out, const float* __restrict__ z) {
    int i = blockIdx.x * blockDim.x + threadIdx.x;
    if (i >= BB * CC * HWSZ) return;
    int hw = i % HWSZ;
    int c  = (i / HWSZ) % CC;
    int b  = i / (HWSZ * CC);
    out[i] += z[((size_t)b * HWSZ + hw) * CC + c];
}

// ================= host launcher =================
extern "C" void kernel_launch(void* const* d_in, const int* in_sizes, int n_in,
                              void* d_out, int out_size) {
    const float* x      = (const float*)d_in[0];
    const float* ln1_w  = (const float*)d_in[1];
    const float* ln1_b  = (const float*)d_in[2];
    const float* ln2_w  = (const float*)d_in[3];
    const float* ln2_b  = (const float*)d_in[4];
    const float* qkv_w  = (const float*)d_in[5];
    const float* qkv_b  = (const float*)d_in[6];
    const float* proj_w = (const float*)d_in[7];
    const float* proj_b = (const float*)d_in[8];
    const float* table  = (const float*)d_in[9];
    const float* fc1_w  = (const float*)d_in[10];
    const float* fc1_b  = (const float*)d_in[11];
    const float* fc2_w  = (const float*)d_in[12];
    const float* fc2_b  = (const float*)d_in[13];
    float* out = (float*)d_out;

    float *p_xf, *p_qkv, *p_o, *p_y1, *p_bias, *p_ln2, *p_hid;
    cudaGetSymbolAddress((void**)&p_xf,  g_xf);
    cudaGetSymbolAddress((void**)&p_qkv, g_qkv);
    cudaGetSymbolAddress((void**)&p_o,   g_o);
    cudaGetSymbolAddress((void**)&p_y1,  g_y1);
    cudaGetSymbolAddress((void**)&p_bias,g_bias);
    cudaGetSymbolAddress((void**)&p_ln2, g_ln2);
    cudaGetSymbolAddress((void**)&p_hid, g_hid);

    cudaFuncSetAttribute(k_gemm, cudaFuncAttributeMaxDynamicSharedMemorySize, GSMEM);

    // launch order arranged so the ncu-captured launch (#4) is the QKV GEMM
    k_bias<<<(NHD * NN * NN + 255) / 256, 256>>>(table, p_bias);          // 1
    k_ln<true><<<BB * HH * 2, dim3(28, 8)>>>(x, ln1_w, ln1_b, p_xf);      // 2
    k_bias<<<(NHD * NN * NN + 255) / 256, 256>>>(table, p_bias);          // 3 (idempotent spacer)

    // attention pass 1
    k_gemm<<<dim3(NPTS / 128, 6), 256, GSMEM>>>(qkv_w, qkv_b, p_xf, p_qkv, CC, 3 * CC, 0);  // 4 <- profiled
    k_attn<<<MM * NHD, 256>>>(p_qkv, p_bias, p_o);
    k_gemm<<<dim3(NPTS / 128, 2), 256, GSMEM>>>(proj_w, proj_b, p_o, p_y1, CC, CC, 0);

    // attention pass 2
    k_gemm<<<dim3(NPTS / 128, 6), 256, GSMEM>>>(qkv_w, qkv_b, p_y1, p_qkv, CC, 3 * CC, 0);
    k_attn<<<MM * NHD, 256>>>(p_qkv, p_bias, p_o);
    k_gemm<<<dim3(NPTS / 128, 2), 256, GSMEM>>>(proj_w, proj_b, p_o, p_xf, CC, CC, 0);

    // residual + unblock
    k_resid<<<(BB * CC * HWSZ + 255) / 256, 256>>>(x, p_xf, out);

    // LN2 -> (pt, C)
    k_ln<false><<<BB * HH * 2, dim3(28, 8)>>>(out, ln2_w, ln2_b, p_ln2);

    // MLP
    k_gemm<<<dim3(NPTS / 128, HID_ / 128), 256, GSMEM>>>(fc1_w, fc1_b, p_ln2, p_hid, CC, HID_, 1);
    k_gemm<<<dim3(NPTS / 128, CC / 128),  256, GSMEM>>>(fc2_w, fc2_b, p_hid, p_o, HID_, CC, 0);
    k_resid2<<<(BB * CC * HWSZ + 255) / 256, 256>>>(out, p_o);
}

// round 8
// speedup vs baseline: 1.1558x; 1.0149x over previous
#include <cuda_runtime.h>
#include <cuda_bf16.h>
#include <math.h>
#include <stdint.h>

// ---------------- problem constants ----------------
#define BB   16
#define CC   256
#define HH   56
#define HWSZ 3136
#define WWIN 7
#define NN   49
#define MM   1024
#define NHD  8
#define HID_ 1024
#define NPTS 50176
#define EPSV 1e-5f

// ---------------- device scratch ----------------
__device__ float g_xf [(size_t)NPTS * CC];
__device__ float g_qkv[(size_t)NPTS * 3 * CC];
__device__ float g_o  [(size_t)NPTS * CC];
__device__ float g_y1 [(size_t)NPTS * CC];
__device__ float g_ln2[(size_t)NPTS * CC];
__device__ float g_hid[(size_t)NPTS * HID_];
__device__ float g_bias[NHD * NN * NN];

// ================= helpers =================
__device__ __forceinline__ void mma16816(float* c, const uint32_t* a, const uint32_t* b) {
    asm volatile(
        "mma.sync.aligned.m16n8k16.row.col.f32.bf16.bf16.f32 "
        "{%0,%1,%2,%3}, {%4,%5,%6,%7}, {%8,%9}, {%0,%1,%2,%3};"
        : "+f"(c[0]), "+f"(c[1]), "+f"(c[2]), "+f"(c[3])
        : "r"(a[0]), "r"(a[1]), "r"(a[2]), "r"(a[3]), "r"(b[0]), "r"(b[1]));
}
__device__ __forceinline__ void ldsm4(uint32_t* r, uint32_t addr) {
    asm volatile("ldmatrix.sync.aligned.m8n8.x4.shared.b16 {%0,%1,%2,%3}, [%4];"
        : "=r"(r[0]), "=r"(r[1]), "=r"(r[2]), "=r"(r[3]) : "r"(addr));
}
__device__ __forceinline__ uint32_t split2(float x, float y, uint32_t& lo2) {
    __nv_bfloat16 hx = __float2bfloat16(x);
    __nv_bfloat16 hy = __float2bfloat16(y);
    float lx = x - __bfloat162float(hx);
    float ly = y - __bfloat162float(hy);
    __nv_bfloat162 h; h.x = hx; h.y = hy;
    __nv_bfloat162 l; l.x = __float2bfloat16(lx); l.y = __float2bfloat16(ly);
    lo2 = *reinterpret_cast<uint32_t*>(&l);
    return *reinterpret_cast<uint32_t*>(&h);
}
__device__ __forceinline__ uint32_t smem_u32(const void* p) {
    uint32_t a;
    asm("{ .reg .u64 t; cvta.to.shared.u64 t, %1; cvt.u32.u64 %0, t; }" : "=r"(a) : "l"(p));
    return a;
}

// ================= bf16 split GEMM (2 CTAs/SM, ldmatrix, early-stash) =================
#define SPAD  40
#define TILEH (128 * SPAD)
#define GSMEM (8 * TILEH * 2)    // 81920 bytes -> 2 CTAs/SM fits 228KB

__global__ void __launch_bounds__(256, 2)
k_gemm(const float* __restrict__ W, const float* __restrict__ bias,
       const float* __restrict__ X, float* __restrict__ out,
       int IC, int OC, int gelu)
{
    extern __shared__ __align__(16) __nv_bfloat16 sm[];
    __nv_bfloat16* Ahi = sm;
    __nv_bfloat16* Alo = sm + 2 * TILEH;
    __nv_bfloat16* Bhi = sm + 4 * TILEH;
    __nv_bfloat16* Blo = sm + 6 * TILEH;
    const uint32_t sbAh = smem_u32(Ahi), sbAl = smem_u32(Alo);
    const uint32_t sbBh = smem_u32(Bhi), sbBl = smem_u32(Blo);

    const int tid = threadIdx.x, lane = tid & 31, wid = tid >> 5;
    const int p0 = blockIdx.x * 128, o0 = blockIdx.y * 128;
    const int wm = (wid & 1) * 64, wn = (wid >> 1) * 32;
    const int g = lane >> 2, t = lane & 3;
    const int lrow = tid >> 3, lc4 = (tid & 7) << 2;

    // ldmatrix per-lane source coordinates (verified R6/R7)
    const int a_row = (lane & 7) + ((lane >> 3) & 1) * 8;
    const int a_col = (lane >> 4) * 8;
    const int b_row = (lane & 7) + (lane >> 4) * 8;
    const int b_col = ((lane >> 3) & 1) * 8;

    float acc[4][4][4];
    #pragma unroll
    for (int i = 0; i < 4; i++)
        #pragma unroll
        for (int j = 0; j < 4; j++)
            #pragma unroll
            for (int q = 0; q < 4; q++) acc[i][j][q] = 0.f;

    // fetch + immediately split/stash (staging registers die before compute)
    auto fetchstash = [&](int kt, int buf) {
        int c0 = kt * 32;
        #pragma unroll
        for (int half = 0; half < 2; ++half) {
            float4 ra0, ra1, rb0, rb1;
            int r0 = lrow + (half * 2) * 32;
            int r1 = lrow + (half * 2 + 1) * 32;
            ra0 = *reinterpret_cast<const float4*>(X + (size_t)(p0 + r0) * IC + c0 + lc4);
            ra1 = *reinterpret_cast<const float4*>(X + (size_t)(p0 + r1) * IC + c0 + lc4);
            rb0 = *reinterpret_cast<const float4*>(W + (size_t)(o0 + r0) * IC + c0 + lc4);
            rb1 = *reinterpret_cast<const float4*>(W + (size_t)(o0 + r1) * IC + c0 + lc4);
            uint32_t l0, l1, h0, h1;
            int ha0 = buf * TILEH + r0 * SPAD + lc4;
            int ha1 = buf * TILEH + r1 * SPAD + lc4;
            h0 = split2(ra0.x, ra0.y, l0); h1 = split2(ra0.z, ra0.w, l1);
            *reinterpret_cast<uint2*>(&Ahi[ha0]) = make_uint2(h0, h1);
            *reinterpret_cast<uint2*>(&Alo[ha0]) = make_uint2(l0, l1);
            h0 = split2(ra1.x, ra1.y, l0); h1 = split2(ra1.z, ra1.w, l1);
            *reinterpret_cast<uint2*>(&Ahi[ha1]) = make_uint2(h0, h1);
            *reinterpret_cast<uint2*>(&Alo[ha1]) = make_uint2(l0, l1);
            h0 = split2(rb0.x, rb0.y, l0); h1 = split2(rb0.z, rb0.w, l1);
            *reinterpret_cast<uint2*>(&Bhi[ha0]) = make_uint2(h0, h1);
            *reinterpret_cast<uint2*>(&Blo[ha0]) = make_uint2(l0, l1);
            h0 = split2(rb1.x, rb1.y, l0); h1 = split2(rb1.z, rb1.w, l1);
            *reinterpret_cast<uint2*>(&Bhi[ha1]) = make_uint2(h0, h1);
            *reinterpret_cast<uint2*>(&Blo[ha1]) = make_uint2(l0, l1);
        }
    };

    // compute with sequenced fragment loads (peak frag regs ~40)
    auto compute = [&](int buf) {
        #pragma unroll
        for (int k0 = 0; k0 < 32; k0 += 16) {
            uint32_t ah[4][4], bx[2][4];
            #pragma unroll
            for (int i = 0; i < 4; i++) {
                uint32_t off = (uint32_t)((buf * TILEH + (wm + i * 16 + a_row) * SPAD + k0 + a_col) * 2);
                ldsm4(ah[i], sbAh + off);
            }
            #pragma unroll
            for (int j2 = 0; j2 < 2; j2++) {
                uint32_t off = (uint32_t)((buf * TILEH + (wn + j2 * 16 + b_row) * SPAD + k0 + b_col) * 2);
                ldsm4(bx[j2], sbBh + off);
            }
            #pragma unroll
            for (int i = 0; i < 4; i++)
                #pragma unroll
                for (int j = 0; j < 4; j++) mma16816(acc[i][j], ah[i], &bx[j >> 1][(j & 1) * 2]);
            // B-lo term
            uint32_t bl[2][4];
            #pragma unroll
            for (int j2 = 0; j2 < 2; j2++) {
                uint32_t off = (uint32_t)((buf * TILEH + (wn + j2 * 16 + b_row) * SPAD + k0 + b_col) * 2);
                ldsm4(bl[j2], sbBl + off);
            }
            #pragma unroll
            for (int i = 0; i < 4; i++)
                #pragma unroll
                for (int j = 0; j < 4; j++) mma16816(acc[i][j], ah[i], &bl[j >> 1][(j & 1) * 2]);
            // A-lo term (reuse ah registers)
            #pragma unroll
            for (int i = 0; i < 4; i++) {
                uint32_t off = (uint32_t)((buf * TILEH + (wm + i * 16 + a_row) * SPAD + k0 + a_col) * 2);
                ldsm4(ah[i], sbAl + off);
            }
            #pragma unroll
            for (int i = 0; i < 4; i++)
                #pragma unroll
                for (int j = 0; j < 4; j++) mma16816(acc[i][j], ah[i], &bx[j >> 1][(j & 1) * 2]);
        }
    };

    fetchstash(0, 0);
    __syncthreads();
    const int KT = IC >> 5;
    for (int kt = 0; kt < KT; ++kt) {
        int buf = kt & 1;
        if (kt + 1 < KT) fetchstash(kt + 1, buf ^ 1);
        compute(buf);
        __syncthreads();
    }

    // epilogue
    #pragma unroll
    for (int j = 0; j < 4; j++) {
        int col = o0 + wn + j * 8 + 2 * t;
        float b0 = bias[col], b1 = bias[col + 1];
        #pragma unroll
        for (int i = 0; i < 4; i++) {
            int r0 = p0 + wm + i * 16 + g;
            float v0 = acc[i][j][0] + b0, v1 = acc[i][j][1] + b1;
            float v2 = acc[i][j][2] + b0, v3 = acc[i][j][3] + b1;
            if (gelu) {
                v0 = 0.5f * v0 * (1.f + erff(v0 * 0.70710678118654752f));
                v1 = 0.5f * v1 * (1.f + erff(v1 * 0.70710678118654752f));
                v2 = 0.5f * v2 * (1.f + erff(v2 * 0.70710678118654752f));
                v3 = 0.5f * v3 * (1.f + erff(v3 * 0.70710678118654752f));
            }
            *reinterpret_cast<float2*>(&out[(size_t)r0 * OC + col])       = make_float2(v0, v1);
            *reinterpret_cast<float2*>(&out[(size_t)(r0 + 8) * OC + col]) = make_float2(v2, v3);
        }
    }
}

// ================= relative-position bias =================
__global__ void k_bias(const float* __restrict__ table, float* __restrict__ bias) {
    int i = blockIdx.x * blockDim.x + threadIdx.x;
    if (i >= NHD * NN * NN) return;
    int h = i / (NN * NN);
    int rem = i % (NN * NN);
    int n = rem / NN, k = rem % NN;
    int dr = n / WWIN - k / WWIN + (WWIN - 1);
    int dc = n % WWIN - k % WWIN + (WWIN - 1);
    bias[i] = table[(dr * (2 * WWIN - 1) + dc) * NHD + h];
}

// ================= channel LayerNorm: NCHW in, (pt, C) out =================
template <bool BLOCKED>
__global__ void k_ln(const float* __restrict__ x, const float* __restrict__ w,
                     const float* __restrict__ b, float* __restrict__ out) {
    int blk = blockIdx.x;
    int w0  = (blk & 1) * 28;
    int bh  = blk >> 1;
    int h   = bh % HH;
    int bb  = bh / HH;
    int tx = threadIdx.x, ty = threadIdx.y;
    int wpos = w0 + tx;

    const float* xb = x + (size_t)bb * CC * HWSZ + h * HH + wpos;

    float s = 0.f, s2 = 0.f;
    #pragma unroll
    for (int c = ty; c < CC; c += 8) {
        float v = xb[(size_t)c * HWSZ];
        s += v; s2 += v * v;
    }
    __shared__ float sh_s[8][28], sh_s2[8][28];
    __shared__ float sh_mu[28], sh_rs[28];
    sh_s[ty][tx] = s; sh_s2[ty][tx] = s2;
    __syncthreads();
    if (ty == 0) {
        float ts = 0.f, ts2 = 0.f;
        #pragma unroll
        for (int j = 0; j < 8; j++) { ts += sh_s[j][tx]; ts2 += sh_s2[j][tx]; }
        float mu  = ts * (1.f / CC);
        float var = ts2 * (1.f / CC) - mu * mu;
        sh_mu[tx] = mu; sh_rs[tx] = rsqrtf(var + EPSV);
    }
    __syncthreads();
    float mu = sh_mu[tx], rs = sh_rs[tx];

    size_t pt;
    if (BLOCKED) {
        int m = bb * 64 + (h / WWIN) * 8 + (wpos / WWIN);
        int n = (h % WWIN) * WWIN + (wpos % WWIN);
        pt = (size_t)m * NN + n;
    } else {
        pt = (size_t)bb * HWSZ + h * HH + wpos;
    }
    float* ob = out + pt * CC;
    #pragma unroll
    for (int c = ty; c < CC; c += 8)
        ob[c] = (xb[(size_t)c * HWSZ] - mu) * rs * w[c] + b[c];
}

// ================= attention core (R3 verbatim) =================
#define QPAD 36
__global__ void k_attn(const float* __restrict__ qkv, const float* __restrict__ bias,
                       float* __restrict__ out) {
    int m = blockIdx.x >> 3;
    int h = blockIdx.x & 7;

    __shared__ float sq[NN * QPAD], sk[NN * QPAD], sv[NN * QPAD];
    __shared__ float at[NN * 52];

    int tid = threadIdx.x;
    const float* baseq = qkv + (size_t)(m * NN) * (3 * CC) + h * 32;
    #pragma unroll 2
    for (int i = tid; i < NN * 8; i += 256) {
        int n = i >> 3, d4 = (i & 7) << 2;
        const float* rp = baseq + (size_t)n * (3 * CC);
        float4 q4 = *reinterpret_cast<const float4*>(rp + d4);
        float4 k4 = *reinterpret_cast<const float4*>(rp + CC + d4);
        float4 v4 = *reinterpret_cast<const float4*>(rp + 2 * CC + d4);
        *reinterpret_cast<float4*>(&sq[n * QPAD + d4]) = q4;
        *reinterpret_cast<float4*>(&sk[n * QPAD + d4]) = k4;
        *reinterpret_cast<float4*>(&sv[n * QPAD + d4]) = v4;
    }
    __syncthreads();

    const float* bh = bias + h * NN * NN;
    const float scale = 0.17677669529663687f;
    for (int i = tid; i < NN * NN; i += 256) {
        int n = i / NN, kk = i % NN;
        const float4* qr = reinterpret_cast<const float4*>(&sq[n * QPAD]);
        const float4* kr = reinterpret_cast<const float4*>(&sk[kk * QPAD]);
        float s = 0.f;
        #pragma unroll
        for (int d = 0; d < 8; d++) {
            float4 a = qr[d], b = kr[d];
            s += a.x * b.x + a.y * b.y + a.z * b.z + a.w * b.w;
        }
        at[n * 52 + kk] = s * scale + bh[i];
    }
    __syncthreads();

    int warp = tid >> 5, lane = tid & 31;
    for (int n = warp; n < NN; n += 8) {
        float v0 = at[n * 52 + lane];
        float v1 = (lane + 32 < NN) ? at[n * 52 + lane + 32] : -INFINITY;
        float mx = fmaxf(v0, v1);
        #pragma unroll
        for (int o = 16; o; o >>= 1) mx = fmaxf(mx, __shfl_xor_sync(0xffffffffu, mx, o));
        float e0 = __expf(v0 - mx);
        float e1 = (lane + 32 < NN) ? __expf(v1 - mx) : 0.f;
        float s = e0 + e1;
        #pragma unroll
        for (int o = 16; o; o >>= 1) s += __shfl_xor_sync(0xffffffffu, s, o);
        float inv = 1.f / s;
        at[n * 52 + lane] = e0 * inv;
        if (lane + 32 < NN) at[n * 52 + lane + 32] = e1 * inv;
    }
    __syncthreads();

    for (int i = tid; i < NN * 8; i += 256) {
        int n = i >> 3, d4 = (i & 7) << 2;
        float4 accv = make_float4(0.f, 0.f, 0.f, 0.f);
        #pragma unroll 7
        for (int kk = 0; kk < NN; kk++) {
            float wv = at[n * 52 + kk];
            float4 v4 = *reinterpret_cast<const float4*>(&sv[kk * QPAD + d4]);
            accv.x += wv * v4.x; accv.y += wv * v4.y;
            accv.z += wv * v4.z; accv.w += wv * v4.w;
        }
        *reinterpret_cast<float4*>(&out[(size_t)(m * NN + n) * CC + h * 32 + d4]) = accv;
    }
}

// ================= residuals =================
__global__ void k_resid(const float* __restrict__ x, const float* __restrict__ y,
                        float* __restrict__ out) {
    int i = blockIdx.x * blockDim.x + threadIdx.x;
    if (i >= BB * CC * HWSZ) return;
    int w = i % HH; int t = i / HH;
    int h = t % HH;  t /= HH;
    int c = t % CC;  int b = t / CC;
    int m = b * 64 + (h / WWIN) * 8 + (w / WWIN);
    int n = (h % WWIN) * WWIN + (w % WWIN);
    out[i] = x[i] + y[(size_t)(m * NN + n) * CC + c];
}
__global__ void k_resid2(float* __restrict__ out, const float* __restrict__ z) {
    int i = blockIdx.x * blockDim.x + threadIdx.x;
    if (i >= BB * CC * HWSZ) return;
    int hw = i % HWSZ;
    int c  = (i / HWSZ) % CC;
    int b  = i / (HWSZ * CC);
    out[i] += z[((size_t)b * HWSZ + hw) * CC + c];
}

// ================= host launcher =================
extern "C" void kernel_launch(void* const* d_in, const int* in_sizes, int n_in,
                              void* d_out, int out_size) {
    const float* x      = (const float*)d_in[0];
    const float* ln1_w  = (const float*)d_in[1];
    const float* ln1_b  = (const float*)d_in[2];
    const float* ln2_w  = (const float*)d_in[3];
    const float* ln2_b  = (const float*)d_in[4];
    const float* qkv_w  = (const float*)d_in[5];
    const float* qkv_b  = (const float*)d_in[6];
    const float* proj_w = (const float*)d_in[7];
    const float* proj_b = (const float*)d_in[8];
    const float* table  = (const float*)d_in[9];
    const float* fc1_w  = (const float*)d_in[10];
    const float* fc1_b  = (const float*)d_in[11];
    const float* fc2_w  = (const float*)d_in[12];
    const float* fc2_b  = (const float*)d_in[13];
    float* out = (float*)d_out;

    float *p_xf, *p_qkv, *p_o, *p_y1, *p_bias, *p_ln2, *p_hid;
    cudaGetSymbolAddress((void**)&p_xf,  g_xf);
    cudaGetSymbolAddress((void**)&p_qkv, g_qkv);
    cudaGetSymbolAddress((void**)&p_o,   g_o);
    cudaGetSymbolAddress((void**)&p_y1,  g_y1);
    cudaGetSymbolAddress((void**)&p_bias,g_bias);
    cudaGetSymbolAddress((void**)&p_ln2, g_ln2);
    cudaGetSymbolAddress((void**)&p_hid, g_hid);

    cudaFuncSetAttribute(k_gemm, cudaFuncAttributeMaxDynamicSharedMemorySize, GSMEM);

    // launch order arranged so the ncu-captured launch (#4) is the QKV GEMM
    k_bias<<<(NHD * NN * NN + 255) / 256, 256>>>(table, p_bias);          // 1
    k_ln<true><<<BB * HH * 2, dim3(28, 8)>>>(x, ln1_w, ln1_b, p_xf);      // 2
    k_bias<<<(NHD * NN * NN + 255) / 256, 256>>>(table, p_bias);          // 3 (idempotent spacer)

    // attention pass 1
    k_gemm<<<dim3(NPTS / 128, 6), 256, GSMEM>>>(qkv_w, qkv_b, p_xf, p_qkv, CC, 3 * CC, 0);  // 4 <- profiled
    k_attn<<<MM * NHD, 256>>>(p_qkv, p_bias, p_o);
    k_gemm<<<dim3(NPTS / 128, 2), 256, GSMEM>>>(proj_w, proj_b, p_o, p_y1, CC, CC, 0);

    // attention pass 2
    k_gemm<<<dim3(NPTS / 128, 6), 256, GSMEM>>>(qkv_w, qkv_b, p_y1, p_qkv, CC, 3 * CC, 0);
    k_attn<<<MM * NHD, 256>>>(p_qkv, p_bias, p_o);
    k_gemm<<<dim3(NPTS / 128, 2), 256, GSMEM>>>(proj_w, proj_b, p_o, p_xf, CC, CC, 0);

    // residual + unblock
    k_resid<<<(BB * CC * HWSZ + 255) / 256, 256>>>(x, p_xf, out);

    // LN2 -> (pt, C)
    k_ln<false><<<BB * HH * 2, dim3(28, 8)>>>(out, ln2_w, ln2_b, p_ln2);

    // MLP
    k_gemm<<<dim3(NPTS / 128, HID_ / 128), 256, GSMEM>>>(fc1_w, fc1_b, p_ln2, p_hid, CC, HID_, 1);
    k_gemm<<<dim3(NPTS / 128, CC / 128),  256, GSMEM>>>(fc2_w, fc2_b, p_hid, p_o, HID_, CC, 0);
    k_resid2<<<(BB * CC * HWSZ + 255) / 256, 256>>>(out, p_o);
}